// round 4
// baseline (speedup 1.0000x reference)
#include <cuda_runtime.h>
#include <cuda_fp16.h>

// Problem shape (fixed by the dataset)
#define BATCH 8
#define CHAN  3
#define HH    720
#define WW    1280
#define HW    (HH * WW)
#define NROWS (BATCH * HH)
#define EPSV  1e-6f
// log2(1.414) to float precision
#define K_LOG2 0.49978218f

// Per-bin accumulator packed as 4 x f16 in one 64-bit word:
//   low  f16x2 = (c0, c1), high f16x2 = (c2, wsum)
// Accumulated with ONE red.global.add.noftz.v2.f16x2 per (pixel, bin) —
// 2 REDs/pixel vs 4 shared ATOMS/pixel in R3. The R3 profile showed the
// l1tex pipe at 83% (shared-atomic passes); REDs are executed by the 184
// L2/LTS atomic ALUs instead, costing l1tex ~1 wavefront per instruction.
//
// Each row's 10KB scratch slice is zeroed, accumulated, read back and then
// L2-discarded inside one block, so the 59MB scratch never round-trips DRAM.
__device__ __align__(128) unsigned long long g_scratch[(size_t)NROWS * WW];

__device__ __forceinline__ void red_v2f16x2(unsigned long long* p,
                                            unsigned lo, unsigned hi) {
    asm volatile("red.global.add.noftz.v2.f16x2 [%0], {%1, %2};"
                 :: "l"(p), "r"(lo), "r"(hi) : "memory");
}

__device__ __forceinline__ unsigned pack_h2(float a, float b) {
    __half2 h = __floats2half2_rn(a, b);
    return *(unsigned*)&h;
}

__global__ __launch_bounds__(320) void splat_kernel(
    const float* __restrict__ im,
    const float* __restrict__ disp,
    float* __restrict__ out)
{
    const int row = blockIdx.x;      // b*HH + y
    const int b   = row / HH;
    const int y   = row - b * HH;
    const int tid = threadIdx.x;

    unsigned long long* srow = g_scratch + (size_t)row * WW;

    // ---- phase 0: zero this row's scratch (1280 * 8B = 640 uint4) ----
    {
        uint4 z = make_uint4(0u, 0u, 0u, 0u);
        ((uint4*)srow)[2 * tid]     = z;
        ((uint4*)srow)[2 * tid + 1] = z;
    }
    __syncthreads();   // zeros visible before any RED from this block

    // ---- phase 1: splat — 4 consecutive pixels per thread ----
    const float4* d_row4 = (const float4*)(disp + (size_t)row * WW);
    const float*  im_row = im  + (size_t)b * CHAN * HW + (size_t)y * WW;
    float*        o_row  = out + (size_t)b * CHAN * HW + (size_t)y * WW;

    const int xb = tid * 4;
    float4 d4 = d_row4[tid];
    float4 c0 = ((const float4*)(im_row))[tid];
    float4 c1 = ((const float4*)(im_row + HW))[tid];
    float4 c2 = ((const float4*)(im_row + 2 * HW))[tid];

    const float dd[4] = {d4.x, d4.y, d4.z, d4.w};
    const float p0[4] = {c0.x, c0.y, c0.z, c0.w};
    const float p1[4] = {c1.x, c1.y, c1.z, c1.w};
    const float p2[4] = {c2.x, c2.y, c2.z, c2.w};

    #pragma unroll
    for (int k = 0; k < 4; k++) {
        float d = dd[k];
        float w;
        asm("ex2.approx.f32 %0, %1;" : "=f"(w) : "f"(d * K_LOG2));
        float tx  = (float)(xb + k) - d;
        float x0f = floorf(tx);
        int   x0  = (int)x0f;
        float fc  = tx - x0f;        // weight toward x0+1
        float wc  = w * fc;          // combined weight at x0+1
        float wa  = w - wc;          // combined weight at x0

        float v0 = p0[k], v1 = p1[k], v2 = p2[k];

        if ((unsigned)x0 < WW) {     // x0 may be as low as -21; x0 <= x always
            red_v2f16x2(srow + x0,
                        pack_h2(v0 * wa, v1 * wa),
                        pack_h2(v2 * wa, wa));
        }
        int x1 = x0 + 1;
        if ((unsigned)x1 < WW) {
            red_v2f16x2(srow + x1,
                        pack_h2(v0 * wc, v1 * wc),
                        pack_h2(v2 * wc, wc));
        }
    }

    // make this block's posted REDs visible to this block's reads
    __threadfence();
    __syncthreads();

    // ---- phase 2: normalize — read back 4 bins (32B) per thread ----
    uint4 qa = ((const uint4*)srow)[2 * tid];       // bins 4t, 4t+1
    uint4 qb = ((const uint4*)srow)[2 * tid + 1];   // bins 4t+2, 4t+3
    const unsigned lo[4] = {qa.x, qa.z, qb.x, qb.z};  // (c0,c1) per bin
    const unsigned hi[4] = {qa.y, qa.w, qb.y, qb.w};  // (c2,w)  per bin

    float4 r0, r1, r2;
    float* r0p = &r0.x; float* r1p = &r1.x; float* r2p = &r2.x;
    #pragma unroll
    for (int j = 0; j < 4; j++) {
        __half2 a  = *(const __half2*)&lo[j];
        __half2 bb = *(const __half2*)&hi[j];
        float n0 = __low2float(a),  n1 = __high2float(a);
        float n2 = __low2float(bb), ws = __high2float(bb);
        float inv = 1.0f / fmaxf(ws, EPSV);
        r0p[j] = n0 * inv;
        r1p[j] = n1 * inv;
        r2p[j] = n2 * inv;
    }

    // scratch values consumed -> discard the 128B line (no DRAM writeback).
    // Each line covers threads 4k..4k+3; all lanes have consumed their loads
    // (values feed the arithmetic above), syncwarp publishes that.
    __syncwarp();
    if ((tid & 3) == 0)
        asm volatile("discard.global.L2 [%0], 128;" :: "l"(srow + 4 * tid));

    ((float4*)o_row)[tid]            = r0;
    ((float4*)(o_row + HW))[tid]     = r1;
    ((float4*)(o_row + 2 * HW))[tid] = r2;
}

extern "C" void kernel_launch(void* const* d_in, const int* in_sizes, int n_in,
                              void* d_out, int out_size) {
    const float* im   = (const float*)d_in[0];   // [8,3,720,1280] fp32
    const float* disp = (const float*)d_in[1];   // [8,1,720,1280] fp32
    float* out = (float*)d_out;                  // [8,3,720,1280] fp32

    splat_kernel<<<NROWS, 320>>>(im, disp, out);
}

// round 5
// speedup vs baseline: 1.2021x; 1.2021x over previous
#include <cuda_runtime.h>
#include <cuda_fp16.h>

// Problem shape (fixed by the dataset)
#define BATCH 8
#define CHAN  3
#define HH    720
#define WW    1280
#define HW    (HH * WW)
#define NROWS (BATCH * HH)
#define EPSV  1e-6f
#define K_LOG2 0.49978218f     // log2(1.414)

// flow_y == 0 -> 1-D splat: pixel x hits bins x0=floor(x-d) (weight wa) and
// x0+1 (weight wc). Four f16 accumulators per bin: c0,c1,c2,wsum.
//
// Hybrid accumulation (R3 was shared-pipe bound at 83% l1tex, R4 all-global
// was LTS bound): (c0,c1) accumulate via 2 shared f16x2 atomics per pixel,
// (c2,w) accumulate via ONE red.global.add.noftz.v2.f16x2 per pixel.
// The global plane co-locates both bilinear pieces at slot x0+1:
//   entry[s].lo = (c2*wa, wa)   -> piece1 of bin s-1
//   entry[s].hi = (c2*wc, wc)   -> piece2 of bin s
// merge: bin j = entry[j+1].lo + entry[j].hi. Slots s in [0, WW].
//
// Row stride padded to 1296 entries (81 * 128B) so per-row L2 discard lines
// never cross rows.
#define RSTRIDE 1296
__device__ __align__(128) unsigned long long g_pl[(size_t)NROWS * RSTRIDE];

__device__ __forceinline__ void red_v2f16x2(unsigned long long* p,
                                            unsigned lo, unsigned hi) {
    asm volatile("red.global.add.noftz.v2.f16x2 [%0], {%1, %2};"
                 :: "l"(p), "r"(lo), "r"(hi) : "memory");
}
__device__ __forceinline__ unsigned pack_h2(float a, float b) {
    __half2 h = __floats2half2_rn(a, b);
    return *(unsigned*)&h;
}

__global__ __launch_bounds__(320) void splat_kernel(
    const float* __restrict__ im,
    const float* __restrict__ disp,
    float* __restrict__ out)
{
    __shared__ __half2 sA[WW];   // (c0, c1) per bin (5 KB)

    const int row = blockIdx.x;      // b*HH + y
    const int b   = row / HH;
    const int y   = row - b * HH;
    const int tid = threadIdx.x;

    unsigned long long* srow = g_pl + (size_t)row * RSTRIDE;

    // ---- phase 0: zero shared plane + global plane slots [0, WW] ----
    ((uint4*)sA)[tid] = make_uint4(0u, 0u, 0u, 0u);
    {
        uint4 z = make_uint4(0u, 0u, 0u, 0u);
        ((uint4*)srow)[2 * tid]     = z;   // slots 4t, 4t+1
        ((uint4*)srow)[2 * tid + 1] = z;   // slots 4t+2, 4t+3
        if (tid == 0) srow[WW] = 0ull;     // slot 1280
    }
    __syncthreads();   // zeros visible before any atomic from this block

    // ---- phase 1: splat, 4 consecutive pixels per thread ----
    const float4* d_row4 = (const float4*)(disp + (size_t)row * WW);
    const float*  im_row = im  + (size_t)b * CHAN * HW + (size_t)y * WW;
    float*        o_row  = out + (size_t)b * CHAN * HW + (size_t)y * WW;

    const int xb = tid * 4;
    float4 d4 = d_row4[tid];
    float4 c0 = ((const float4*)(im_row))[tid];
    float4 c1 = ((const float4*)(im_row + HW))[tid];
    float4 c2 = ((const float4*)(im_row + 2 * HW))[tid];

    const float dd[4] = {d4.x, d4.y, d4.z, d4.w};
    const float p0[4] = {c0.x, c0.y, c0.z, c0.w};
    const float p1[4] = {c1.x, c1.y, c1.z, c1.w};
    const float p2[4] = {c2.x, c2.y, c2.z, c2.w};

    #pragma unroll
    for (int k = 0; k < 4; k++) {
        float d = dd[k];
        float w;
        asm("ex2.approx.f32 %0, %1;" : "=f"(w) : "f"(d * K_LOG2));
        float tx  = (float)(xb + k) - d;
        float x0f = floorf(tx);
        int   x0  = (int)x0f;
        float fc  = tx - x0f;
        float wc  = w * fc;          // piece toward bin x0+1
        float wa  = w - wc;          // piece toward bin x0

        float v0 = p0[k], v1 = p1[k], v2 = p2[k];

        // shared: (c0,c1)
        if ((unsigned)x0 < WW)
            atomicAdd(&sA[x0], __floats2half2_rn(v0 * wa, v1 * wa));
        int x1 = x0 + 1;
        if ((unsigned)x1 < WW)
            atomicAdd(&sA[x1], __floats2half2_rn(v0 * wc, v1 * wc));

        // global: (c2,w), both pieces in one RED at slot x0+1
        int slot = x0 + 1;           // in [-20, WW]; valid if >= 0
        if (slot >= 0)
            red_v2f16x2(srow + slot,
                        pack_h2(v2 * wa, wa),
                        pack_h2(v2 * wc, wc));
    }

    __threadfence();   // make this block's posted REDs visible to its reads
    __syncthreads();

    // ---- phase 2: merge + normalize ----
    // global: bins xb..xb+3 need slots xb..xb+4
    uint4 qa = ((const uint4*)srow)[2 * tid];       // slots xb, xb+1
    uint4 qb = ((const uint4*)srow)[2 * tid + 1];   // slots xb+2, xb+3
    unsigned long long qc = srow[xb + 4];           // slot xb+4
    unsigned qcl = (unsigned)qc;

    // entry layout: .x/.z = lo(piece1), .y/.w = hi(piece2)
    unsigned mlo[4] = {qa.z, qb.x, qb.z, qcl};  // lo(slot j+1)
    unsigned mhi[4] = {qa.y, qa.w, qb.y, qb.w}; // hi(slot j)

    // shared: (c0,c1) for bins xb..xb+3
    uint4 ua = ((const uint4*)sA)[tid];
    const unsigned va[4] = {ua.x, ua.y, ua.z, ua.w};

    float4 r0, r1, r2;
    float* r0p = &r0.x; float* r1p = &r1.x; float* r2p = &r2.x;
    #pragma unroll
    for (int j = 0; j < 4; j++) {
        __half2 cw = __hadd2(*(const __half2*)&mlo[j],
                             *(const __half2*)&mhi[j]);   // (c2, w)
        __half2 ab = *(const __half2*)&va[j];             // (c0, c1)
        float n0 = __low2float(ab), n1 = __high2float(ab);
        float n2 = __low2float(cw), ws = __high2float(cw);
        float inv = 1.0f / fmaxf(ws, EPSV);
        r0p[j] = n0 * inv;
        r1p[j] = n1 * inv;
        r2p[j] = n2 * inv;
    }

    // all loads from scratch done block-wide -> discard lines (no writeback)
    __syncthreads();
    if (tid < 81)
        asm volatile("discard.global.L2 [%0], 128;"
                     :: "l"((const void*)((const char*)srow + 128 * tid)));

    ((float4*)o_row)[tid]            = r0;
    ((float4*)(o_row + HW))[tid]     = r1;
    ((float4*)(o_row + 2 * HW))[tid] = r2;
}

extern "C" void kernel_launch(void* const* d_in, const int* in_sizes, int n_in,
                              void* d_out, int out_size) {
    const float* im   = (const float*)d_in[0];   // [8,3,720,1280] fp32
    const float* disp = (const float*)d_in[1];   // [8,1,720,1280] fp32
    float* out = (float*)d_out;                  // [8,3,720,1280] fp32

    splat_kernel<<<NROWS, 320>>>(im, disp, out);
}